// round 11
// baseline (speedup 1.0000x reference)
#include <cuda_runtime.h>
#include <math.h>
#include <stdint.h>

#define BB 128
#define TT 512
#define HH 1024
#define EE 128
#define NL 17
#define G3 3072
#define NCTA 128
#define KC 64          // h k-block
#define SHP 68         // h slab row stride (floats)
#define NT 512         // recurrent threads per CTA

// ---------------- device scratch ----------------
__device__ float g_gxw[201326592];            // [B][T][3H]
__device__ uint32_t g_Ahi[67108864];          // we hi  [65536][1024]
__device__ uint32_t g_Alo[67108864];          // we lo
__device__ uint32_t g_Bhi[3145728];           // Wih[:,E:] hi [3072][1024]
__device__ uint32_t g_Blo[3145728];
__device__ float g_tbl[NL * G3];
__device__ float g_hbuf[2][BB * HH];
__device__ volatile unsigned g_pt[BB];        // packed (tag<<5)|pred
__device__ volatile unsigned g_flags[NCTA];

// ---------------- helpers ----------------
__device__ __forceinline__ float sigmoidf_(float x) { return 1.0f / (1.0f + expf(-x)); }

__device__ __forceinline__ float maskval(int prev, int nxt) {
    bool allowed;
    bool prev_open = (prev == 0) || (((prev - 1) & 3) >= 2);   // O, E-, S-
    if (prev_open) {
        allowed = (nxt == 0) || (((nxt - 1) & 3) == 0) || (((nxt - 1) & 3) == 3);
    } else {
        int ty = (prev - 1) >> 2;
        allowed = (nxt != 0) && (((nxt - 1) >> 2) == ty) &&
                  ((((nxt - 1) & 3) == 1) || (((nxt - 1) & 3) == 2));
    }
    return allowed ? 0.0f : -1e12f;
}

__device__ __forceinline__ void flatbar(int cta, int tid, unsigned e) {
    __syncthreads();
    __threadfence();
    if (tid == 0) g_flags[cta] = e;
    if (tid < NCTA) { while (g_flags[tid] < e) { } }
    __syncthreads();
    __threadfence();
}

__device__ __forceinline__ void split_tf32(float x, uint32_t& hi, uint32_t& lo) {
    asm("cvt.rna.tf32.f32 %0, %1;" : "=r"(hi) : "f"(x));
    float hif = __uint_as_float(hi);
    float lof = x - hif;
    asm("cvt.rna.tf32.f32 %0, %1;" : "=r"(lo) : "f"(lof));
}

__device__ __forceinline__ void mma_tf32(float* c, const uint32_t* a,
                                         uint32_t b0, uint32_t b1) {
    asm volatile(
        "mma.sync.aligned.m16n8k8.row.col.f32.tf32.tf32.f32 "
        "{%0,%1,%2,%3}, {%4,%5,%6,%7}, {%8,%9}, {%0,%1,%2,%3};"
        : "+f"(c[0]), "+f"(c[1]), "+f"(c[2]), "+f"(c[3])
        : "r"(a[0]), "r"(a[1]), "r"(a[2]), "r"(a[3]), "r"(b0), "r"(b1));
}

// ---------------- K0: reset persistent state ----------------
__global__ void reset_state() {
    int i = blockIdx.x * blockDim.x + threadIdx.x;
    if (i < BB * HH) g_hbuf[0][i] = 0.0f;
    if (i < NCTA) g_flags[i] = 0u;
    if (i < BB) g_pt[i] = 0u;
}

// ---------------- K1: label-embedding gate table ----------------
__global__ void build_table(const float* __restrict__ label_emb,
                            const float* __restrict__ W_ih,
                            const float* __restrict__ b_ih) {
    int j = blockIdx.x * blockDim.x + threadIdx.x;
    int l = blockIdx.y;
    if (j >= G3) return;
    const float* w = W_ih + (size_t)j * (EE + HH);
    const float* e = label_emb + l * EE;
    float s = b_ih[j];
#pragma unroll 8
    for (int k = 0; k < EE; k++) s += e[k] * w[k];
    g_tbl[l * G3 + j] = s;
}

// ---------------- pre-split kernels (gxw operands, rna) ----------------
__global__ void presplit_A(const float* __restrict__ we) {
    size_t i = (size_t)blockIdx.x * blockDim.x + threadIdx.x;
    size_t stride = (size_t)gridDim.x * blockDim.x;
    size_t n4 = (size_t)BB * TT * HH / 4;
    for (; i < n4; i += stride) {
        float4 v = ((const float4*)we)[i];
        uint4 hi, lo;
        split_tf32(v.x, hi.x, lo.x); split_tf32(v.y, hi.y, lo.y);
        split_tf32(v.z, hi.z, lo.z); split_tf32(v.w, hi.w, lo.w);
        ((uint4*)g_Ahi)[i] = hi;
        ((uint4*)g_Alo)[i] = lo;
    }
}

__global__ void presplit_B(const float* __restrict__ wih) {
    size_t i = (size_t)blockIdx.x * blockDim.x + threadIdx.x;
    size_t stride = (size_t)gridDim.x * blockDim.x;
    size_t n4 = (size_t)G3 * HH / 4;
    for (; i < n4; i += stride) {
        size_t r = i >> 8;
        size_t c4 = (i & 255) * 4;
        float4 v = *(const float4*)&wih[r * (EE + HH) + EE + c4];
        uint4 hi, lo;
        split_tf32(v.x, hi.x, lo.x); split_tf32(v.y, hi.y, lo.y);
        split_tf32(v.z, hi.z, lo.z); split_tf32(v.w, hi.w, lo.w);
        *(uint4*)&g_Bhi[r * HH + c4] = hi;
        *(uint4*)&g_Blo[r * HH + c4] = lo;
    }
}

// ---------------- K2: big GEMM, 3xTF32 TC, pre-split operands ----------------
#define KB 32
#define APAD 36
__global__ __launch_bounds__(256) void gxw_gemm_tc(void) {
    extern __shared__ uint32_t su[];
    uint32_t* sAhi = su;
    uint32_t* sAlo = sAhi + 128 * APAD;
    uint32_t* sBhi = sAlo + 128 * APAD;
    uint32_t* sBlo = sBhi + 256 * APAD;

    const int tid = threadIdx.x;
    const int lane = tid & 31;
    const int warp = tid >> 5;
    const int wm = (warp >> 2) * 64;
    const int wn = (warp & 3) * 64;
    const int m0 = blockIdx.y * 128;
    const int n0 = blockIdx.x * 256;
    const int lr = lane >> 2;
    const int lc = lane & 3;

    float acc[4][8][4];
#pragma unroll
    for (int i = 0; i < 4; i++)
#pragma unroll
        for (int j = 0; j < 8; j++)
#pragma unroll
            for (int q = 0; q < 4; q++) acc[i][j][q] = 0.0f;

    for (int kb = 0; kb < HH; kb += KB) {
        __syncthreads();
#pragma unroll
        for (int jj = 0; jj < 4; jj++) {
            int idx = tid + jj * 256;
            int r = idx >> 3, c4 = (idx & 7) * 4;
            size_t src = (size_t)(m0 + r) * HH + kb + c4;
            *(uint4*)&sAhi[r * APAD + c4] = *(const uint4*)&g_Ahi[src];
            *(uint4*)&sAlo[r * APAD + c4] = *(const uint4*)&g_Alo[src];
        }
#pragma unroll
        for (int jj = 0; jj < 8; jj++) {
            int idx = tid + jj * 256;
            int r = idx >> 3, c4 = (idx & 7) * 4;
            size_t src = (size_t)(n0 + r) * HH + kb + c4;
            *(uint4*)&sBhi[r * APAD + c4] = *(const uint4*)&g_Bhi[src];
            *(uint4*)&sBlo[r * APAD + c4] = *(const uint4*)&g_Blo[src];
        }
        __syncthreads();

#pragma unroll
        for (int ks = 0; ks < KB; ks += 8) {
            uint32_t ah[4][4], al[4][4];
#pragma unroll
            for (int i = 0; i < 4; i++) {
                int row = wm + i * 16 + lr;
                int cc = ks + lc;
                ah[i][0] = sAhi[row * APAD + cc];
                ah[i][1] = sAhi[(row + 8) * APAD + cc];
                ah[i][2] = sAhi[row * APAD + cc + 4];
                ah[i][3] = sAhi[(row + 8) * APAD + cc + 4];
                al[i][0] = sAlo[row * APAD + cc];
                al[i][1] = sAlo[(row + 8) * APAD + cc];
                al[i][2] = sAlo[row * APAD + cc + 4];
                al[i][3] = sAlo[(row + 8) * APAD + cc + 4];
            }
#pragma unroll
            for (int j = 0; j < 8; j++) {
                int cn = wn + j * 8 + lr;
                int ck = ks + lc;
                uint32_t bh0 = sBhi[cn * APAD + ck];
                uint32_t bh1 = sBhi[cn * APAD + ck + 4];
                uint32_t bl0 = sBlo[cn * APAD + ck];
                uint32_t bl1 = sBlo[cn * APAD + ck + 4];
#pragma unroll
                for (int i = 0; i < 4; i++) {
                    mma_tf32(acc[i][j], ah[i], bh0, bh1);
                    mma_tf32(acc[i][j], ah[i], bl0, bl1);
                    mma_tf32(acc[i][j], al[i], bh0, bh1);
                }
            }
        }
    }

#pragma unroll
    for (int i = 0; i < 4; i++) {
#pragma unroll
        for (int j = 0; j < 8; j++) {
            int row = m0 + wm + i * 16 + lr;
            int cn = n0 + wn + j * 8 + lc * 2;
            *(float2*)&g_gxw[(size_t)row * G3 + cn] =
                make_float2(acc[i][j][0], acc[i][j][1]);
            *(float2*)&g_gxw[(size_t)(row + 8) * G3 + cn] =
                make_float2(acc[i][j][2], acc[i][j][3]);
        }
    }
}

// ---------------- K3: persistent recurrent (512 threads, R9 arithmetic) ----
// 128 CTAs x 512 threads. CTA c owns h-cols [8c, 8c+8).
// Thread (g=tid>>6, mi=tid&63): 2 batches (mi, mi+64) x 1 col x 3 gates.
// Per-accumulator FMA chains are bit-identical to R9's (same (b,col) chains,
// same k order); only the thread mapping and gx/hold transport changed.
__global__ __launch_bounds__(NT) void recurrent(const float* __restrict__ Whh,
                                                const float* __restrict__ bhh,
                                                const float* __restrict__ Wout,
                                                const float* __restrict__ bout,
                                                float* __restrict__ out) {
    extern __shared__ float smem[];
    float* shw  = smem;                     // [24][1024]
    float* shh  = shw + 24 * 1024;          // [2][128][SHP]
    float* srow = shh + 2 * BB * SHP;       // [1024]
    __shared__ float slog[NL];

    const int tid = threadIdx.x;
    const int cta = blockIdx.x;
    const int g   = tid >> 6;               // 0..7
    const int mi  = tid & 63;               // 0..63
    const int base = cta * 8;
    const int col  = base + g;
    const int b0 = mi, b1 = mi + 64;

    // one-time: resident W (24 gate rows x 1024)
    for (int f4 = tid; f4 < 24 * 256; f4 += NT) {
        int m = f4 >> 8;
        int q = f4 & 255;
        int wrow = (m >> 3) * HH + base + (m & 7);
        *(float4*)&shw[m * 1024 + q * 4] =
            *(const float4*)&Whh[(size_t)wrow * HH + q * 4];
    }
    const float bhr = bhh[col];
    const float bhz = bhh[HH + col];
    const float bhn = bhh[2 * HH + col];
    __syncthreads();

    const float* wrow_r = &shw[g * 1024];
    const float* wrow_z = &shw[(8 + g) * 1024];
    const float* wrow_n = &shw[(16 + g) * 1024];

    int cur = 0;
    for (int t = 0; t < TT; t++) {
        const float* __restrict__ hin = g_hbuf[cur];
        float* __restrict__ hout = g_hbuf[cur ^ 1];

        // ---- early scattered loads: gx (6) + hold (2); hidden under k-loop ----
        float gx0r, gx0z, gx0n, gx1r, gx1z, gx1n, hold0, hold1;
        {
            size_t r0 = ((size_t)b0 * TT + t) * G3;
            size_t r1 = ((size_t)b1 * TT + t) * G3;
            gx0r = __ldg(&g_gxw[r0 + col]);
            gx0z = __ldg(&g_gxw[r0 + HH + col]);
            gx0n = __ldg(&g_gxw[r0 + 2 * HH + col]);
            gx1r = __ldg(&g_gxw[r1 + col]);
            gx1z = __ldg(&g_gxw[r1 + HH + col]);
            gx1n = __ldg(&g_gxw[r1 + 2 * HH + col]);
            hold0 = hin[b0 * HH + col];
            hold1 = hin[b1 * HH + col];
        }

        // ---- prefetch + store h block 0 (2048 float4, 4/thread) ----
        float4 pf[4];
#pragma unroll
        for (int j = 0; j < 4; j++) {
            int f = tid + j * NT;
            int r = f >> 4, kq = f & 15;
            pf[j] = *(const float4*)&hin[r * HH + kq * 4];
        }
#pragma unroll
        for (int j = 0; j < 4; j++) {
            int f = tid + j * NT;
            int r = f >> 4, kq = f & 15;
            *(float4*)&shh[r * SHP + kq * 4] = pf[j];
        }
        __syncthreads();

        float ar0 = 0.f, az0 = 0.f, an0 = 0.f;
        float ar1 = 0.f, az1 = 0.f, an1 = 0.f;

        for (int kb = 0; kb < HH; kb += KC) {
            const int buf = (kb >> 6) & 1;
            const float* hb = shh + buf * BB * SHP;

            // gmem prefetch of next slab into regs (overlaps compute)
            if (kb + KC < HH) {
#pragma unroll
                for (int j = 0; j < 4; j++) {
                    int f = tid + j * NT;
                    int r = f >> 4, kq = f & 15;
                    pf[j] = *(const float4*)&hin[r * HH + kb + KC + kq * 4];
                }
            }

#pragma unroll 4
            for (int kk = 0; kk < KC; kk += 4) {
                float4 wr = *(const float4*)&wrow_r[kb + kk];
                float4 wz = *(const float4*)&wrow_z[kb + kk];
                float4 wn = *(const float4*)&wrow_n[kb + kk];
                float4 h0 = *(const float4*)&hb[b0 * SHP + kk];
                float4 h1 = *(const float4*)&hb[b1 * SHP + kk];
                ar0 += h0.x * wr.x + h0.y * wr.y + h0.z * wr.z + h0.w * wr.w;
                az0 += h0.x * wz.x + h0.y * wz.y + h0.z * wz.z + h0.w * wz.w;
                an0 += h0.x * wn.x + h0.y * wn.y + h0.z * wn.z + h0.w * wn.w;
                ar1 += h1.x * wr.x + h1.y * wr.y + h1.z * wr.z + h1.w * wr.w;
                az1 += h1.x * wz.x + h1.y * wz.y + h1.z * wz.z + h1.w * wz.w;
                an1 += h1.x * wn.x + h1.y * wn.y + h1.z * wn.z + h1.w * wn.w;
            }

            // store prefetched next slab
            if (kb + KC < HH) {
                float* nb = shh + (buf ^ 1) * BB * SHP;
#pragma unroll
                for (int j = 0; j < 4; j++) {
                    int f = tid + j * NT;
                    int r = f >> 4, kq = f & 15;
                    *(float4*)&nb[r * SHP + kq * 4] = pf[j];
                }
            }
            __syncthreads();
        }

        // ---- epilogue: spin for prev labels, GRU update (R9 expressions) ----
        {
            unsigned v = g_pt[b0];
            while ((v >> 5) < (unsigned)t) v = g_pt[b0];
            const float* tb = g_tbl + (v & 31u) * G3;
            float r = sigmoidf_(gx0r + tb[col] + ar0 + bhr);
            float z = sigmoidf_(gx0z + tb[HH + col] + az0 + bhz);
            float n = tanhf(gx0n + tb[2 * HH + col] + r * (an0 + bhn));
            hout[b0 * HH + col] = (1.0f - z) * n + z * hold0;
        }
        {
            unsigned v = g_pt[b1];
            while ((v >> 5) < (unsigned)t) v = g_pt[b1];
            const float* tb = g_tbl + (v & 31u) * G3;
            float r = sigmoidf_(gx1r + tb[col] + ar1 + bhr);
            float z = sigmoidf_(gx1z + tb[HH + col] + az1 + bhz);
            float n = tanhf(gx1n + tb[2 * HH + col] + r * (an1 + bhn));
            hout[b1 * HH + col] = (1.0f - z) * n + z * hold1;
        }

        flatbar(cta, tid, (unsigned)(t + 1));

        // ---- phase 2: logits + masked argmax; CTA b handles batch row b ----
        {
            const int b = cta;
            if (tid < 256)
                ((float4*)srow)[tid] = ((const float4*)&hout[b * HH])[tid];
            __syncthreads();
            int w = tid >> 5, lane = tid & 31;
            for (int l = w; l < NL; l += 16) {
                float s = 0.0f;
                const float* wo = Wout + (size_t)l * HH;
#pragma unroll 8
                for (int k = lane; k < HH; k += 32) s += srow[k] * __ldg(&wo[k]);
#pragma unroll
                for (int off = 16; off > 0; off >>= 1)
                    s += __shfl_down_sync(0xffffffffu, s, off);
                if (lane == 0) slog[l] = s;
            }
            __syncthreads();
            if (tid == 0) {
                int pv = (int)(g_pt[b] & 31u);
                float best = -INFINITY;
                int bi = 0;
                float* orow = out + ((size_t)b * TT + t) * NL;
#pragma unroll
                for (int l = 0; l < NL; l++) {
                    float v = slog[l] + bout[l] + maskval(pv, l);
                    orow[l] = v;
                    if (v > best) { best = v; bi = l; }
                }
                g_pt[b] = ((unsigned)(t + 1) << 5) | (unsigned)bi;
            }
            __syncthreads();
        }
        cur ^= 1;
    }
}

// ---------------- launch ----------------
extern "C" void kernel_launch(void* const* d_in, const int* in_sizes, int n_in,
                              void* d_out, int out_size) {
    const float* we   = (const float*)d_in[0];
    const float* lemb = (const float*)d_in[1];
    const float* wih  = (const float*)d_in[2];
    const float* whh  = (const float*)d_in[3];
    const float* bih  = (const float*)d_in[4];
    const float* bhh  = (const float*)d_in[5];
    const float* wout = (const float*)d_in[6];
    const float* bout = (const float*)d_in[7];
    float* out = (float*)d_out;

    const int sh_gemm = (2 * 128 * APAD + 2 * 256 * APAD) * 4;        // 110,592 B
    const int sh_rec  = (24 * 1024 + 2 * BB * SHP + 1024) * 4;        // 171,264 B
    cudaFuncSetAttribute(gxw_gemm_tc, cudaFuncAttributeMaxDynamicSharedMemorySize,
                         sh_gemm);
    cudaFuncSetAttribute(recurrent, cudaFuncAttributeMaxDynamicSharedMemorySize,
                         sh_rec);

    reset_state<<<512, 256>>>();
    build_table<<<dim3(G3 / 256, NL), 256>>>(lemb, wih, bih);
    presplit_A<<<4096, 256>>>(we);
    presplit_B<<<768, 256>>>(wih);
    gxw_gemm_tc<<<dim3(G3 / 256, (BB * TT) / 128), 256, sh_gemm>>>();
    recurrent<<<NCTA, NT, sh_rec>>>(whh, bhh, wout, bout, out);
}

// round 12
// speedup vs baseline: 1.2013x; 1.2013x over previous
#include <cuda_runtime.h>
#include <math.h>
#include <stdint.h>

#define BB 128
#define TT 512
#define HH 1024
#define EE 128
#define NL 17
#define G3 3072
#define NCTA 128
#define KC 64          // h k-block
#define SHP 68         // h slab row stride (floats)
#define GXP 132        // sgx row stride

// ---------------- device scratch ----------------
__device__ float g_gxw[201326592];            // [B][T][3H]
__device__ uint32_t g_Ahi[67108864];          // we hi  [65536][1024]
__device__ uint32_t g_Alo[67108864];          // we lo
__device__ uint32_t g_Bhi[3145728];           // Wih[:,E:] hi [3072][1024]
__device__ uint32_t g_Blo[3145728];
__device__ float g_tbl[NL * G3];
__device__ float g_hbuf[2][BB * HH];
__device__ volatile unsigned g_pt[BB];        // packed (tag<<5)|pred
__device__ volatile unsigned g_flags[NCTA];

// ---------------- helpers ----------------
__device__ __forceinline__ float sigmoidf_(float x) { return 1.0f / (1.0f + expf(-x)); }

__device__ __forceinline__ float maskval(int prev, int nxt) {
    bool allowed;
    bool prev_open = (prev == 0) || (((prev - 1) & 3) >= 2);   // O, E-, S-
    if (prev_open) {
        allowed = (nxt == 0) || (((nxt - 1) & 3) == 0) || (((nxt - 1) & 3) == 3);
    } else {
        int ty = (prev - 1) >> 2;
        allowed = (nxt != 0) && (((nxt - 1) >> 2) == ty) &&
                  ((((nxt - 1) & 3) == 1) || (((nxt - 1) & 3) == 2));
    }
    return allowed ? 0.0f : -1e12f;
}

__device__ __forceinline__ void flatbar(int cta, int tid, unsigned e) {
    __syncthreads();
    __threadfence();
    if (tid == 0) g_flags[cta] = e;
    if (tid < NCTA) { while (g_flags[tid] < e) { } }
    __syncthreads();
    __threadfence();
}

__device__ __forceinline__ void split_tf32(float x, uint32_t& hi, uint32_t& lo) {
    asm("cvt.rna.tf32.f32 %0, %1;" : "=r"(hi) : "f"(x));
    float hif = __uint_as_float(hi);
    float lof = x - hif;
    asm("cvt.rna.tf32.f32 %0, %1;" : "=r"(lo) : "f"(lof));
}

__device__ __forceinline__ void mma_tf32(float* c, const uint32_t* a,
                                         uint32_t b0, uint32_t b1) {
    asm volatile(
        "mma.sync.aligned.m16n8k8.row.col.f32.tf32.tf32.f32 "
        "{%0,%1,%2,%3}, {%4,%5,%6,%7}, {%8,%9}, {%0,%1,%2,%3};"
        : "+f"(c[0]), "+f"(c[1]), "+f"(c[2]), "+f"(c[3])
        : "r"(a[0]), "r"(a[1]), "r"(a[2]), "r"(a[3]), "r"(b0), "r"(b1));
}

// ---------------- packed f32x2 helpers (each 32-bit lane = independent fp32)
typedef unsigned long long u64;
__device__ __forceinline__ u64 dup2(float x) {
    u64 r; asm("mov.b64 %0, {%1, %1};" : "=l"(r) : "f"(x)); return r;
}
__device__ __forceinline__ u64 mul2(u64 a, u64 b) {
    u64 d; asm("mul.rn.f32x2 %0, %1, %2;" : "=l"(d) : "l"(a), "l"(b)); return d;
}
__device__ __forceinline__ u64 fma2(u64 a, u64 b, u64 c) {
    u64 d; asm("fma.rn.f32x2 %0, %1, %2, %3;" : "=l"(d) : "l"(a), "l"(b), "l"(c)); return d;
}
__device__ __forceinline__ u64 add2(u64 a, u64 b) {
    u64 d; asm("add.rn.f32x2 %0, %1, %2;" : "=l"(d) : "l"(a), "l"(b)); return d;
}
__device__ __forceinline__ float2 upk2(u64 a) {
    float2 v; asm("mov.b64 {%0, %1}, %2;" : "=f"(v.x), "=f"(v.y) : "l"(a)); return v;
}

// ---------------- K0: reset persistent state ----------------
__global__ void reset_state() {
    int i = blockIdx.x * blockDim.x + threadIdx.x;
    if (i < BB * HH) g_hbuf[0][i] = 0.0f;
    if (i < NCTA) g_flags[i] = 0u;
    if (i < BB) g_pt[i] = 0u;
}

// ---------------- K1: label-embedding gate table ----------------
__global__ void build_table(const float* __restrict__ label_emb,
                            const float* __restrict__ W_ih,
                            const float* __restrict__ b_ih) {
    int j = blockIdx.x * blockDim.x + threadIdx.x;
    int l = blockIdx.y;
    if (j >= G3) return;
    const float* w = W_ih + (size_t)j * (EE + HH);
    const float* e = label_emb + l * EE;
    float s = b_ih[j];
#pragma unroll 8
    for (int k = 0; k < EE; k++) s += e[k] * w[k];
    g_tbl[l * G3 + j] = s;
}

// ---------------- pre-split kernels (gxw operands, rna) ----------------
__global__ void presplit_A(const float* __restrict__ we) {
    size_t i = (size_t)blockIdx.x * blockDim.x + threadIdx.x;
    size_t stride = (size_t)gridDim.x * blockDim.x;
    size_t n4 = (size_t)BB * TT * HH / 4;
    for (; i < n4; i += stride) {
        float4 v = ((const float4*)we)[i];
        uint4 hi, lo;
        split_tf32(v.x, hi.x, lo.x); split_tf32(v.y, hi.y, lo.y);
        split_tf32(v.z, hi.z, lo.z); split_tf32(v.w, hi.w, lo.w);
        ((uint4*)g_Ahi)[i] = hi;
        ((uint4*)g_Alo)[i] = lo;
    }
}

__global__ void presplit_B(const float* __restrict__ wih) {
    size_t i = (size_t)blockIdx.x * blockDim.x + threadIdx.x;
    size_t stride = (size_t)gridDim.x * blockDim.x;
    size_t n4 = (size_t)G3 * HH / 4;
    for (; i < n4; i += stride) {
        size_t r = i >> 8;
        size_t c4 = (i & 255) * 4;
        float4 v = *(const float4*)&wih[r * (EE + HH) + EE + c4];
        uint4 hi, lo;
        split_tf32(v.x, hi.x, lo.x); split_tf32(v.y, hi.y, lo.y);
        split_tf32(v.z, hi.z, lo.z); split_tf32(v.w, hi.w, lo.w);
        *(uint4*)&g_Bhi[r * HH + c4] = hi;
        *(uint4*)&g_Blo[r * HH + c4] = lo;
    }
}

// ---------------- K2: big GEMM, 3xTF32 TC, pre-split operands ----------------
#define KB 32
#define APAD 36
__global__ __launch_bounds__(256) void gxw_gemm_tc(void) {
    extern __shared__ uint32_t su[];
    uint32_t* sAhi = su;
    uint32_t* sAlo = sAhi + 128 * APAD;
    uint32_t* sBhi = sAlo + 128 * APAD;
    uint32_t* sBlo = sBhi + 256 * APAD;

    const int tid = threadIdx.x;
    const int lane = tid & 31;
    const int warp = tid >> 5;
    const int wm = (warp >> 2) * 64;
    const int wn = (warp & 3) * 64;
    const int m0 = blockIdx.y * 128;
    const int n0 = blockIdx.x * 256;
    const int lr = lane >> 2;
    const int lc = lane & 3;

    float acc[4][8][4];
#pragma unroll
    for (int i = 0; i < 4; i++)
#pragma unroll
        for (int j = 0; j < 8; j++)
#pragma unroll
            for (int q = 0; q < 4; q++) acc[i][j][q] = 0.0f;

    for (int kb = 0; kb < HH; kb += KB) {
        __syncthreads();
#pragma unroll
        for (int jj = 0; jj < 4; jj++) {
            int idx = tid + jj * 256;
            int r = idx >> 3, c4 = (idx & 7) * 4;
            size_t src = (size_t)(m0 + r) * HH + kb + c4;
            *(uint4*)&sAhi[r * APAD + c4] = *(const uint4*)&g_Ahi[src];
            *(uint4*)&sAlo[r * APAD + c4] = *(const uint4*)&g_Alo[src];
        }
#pragma unroll
        for (int jj = 0; jj < 8; jj++) {
            int idx = tid + jj * 256;
            int r = idx >> 3, c4 = (idx & 7) * 4;
            size_t src = (size_t)(n0 + r) * HH + kb + c4;
            *(uint4*)&sBhi[r * APAD + c4] = *(const uint4*)&g_Bhi[src];
            *(uint4*)&sBlo[r * APAD + c4] = *(const uint4*)&g_Blo[src];
        }
        __syncthreads();

#pragma unroll
        for (int ks = 0; ks < KB; ks += 8) {
            uint32_t ah[4][4], al[4][4];
#pragma unroll
            for (int i = 0; i < 4; i++) {
                int row = wm + i * 16 + lr;
                int cc = ks + lc;
                ah[i][0] = sAhi[row * APAD + cc];
                ah[i][1] = sAhi[(row + 8) * APAD + cc];
                ah[i][2] = sAhi[row * APAD + cc + 4];
                ah[i][3] = sAhi[(row + 8) * APAD + cc + 4];
                al[i][0] = sAlo[row * APAD + cc];
                al[i][1] = sAlo[(row + 8) * APAD + cc];
                al[i][2] = sAlo[row * APAD + cc + 4];
                al[i][3] = sAlo[(row + 8) * APAD + cc + 4];
            }
#pragma unroll
            for (int j = 0; j < 8; j++) {
                int cn = wn + j * 8 + lr;
                int ck = ks + lc;
                uint32_t bh0 = sBhi[cn * APAD + ck];
                uint32_t bh1 = sBhi[cn * APAD + ck + 4];
                uint32_t bl0 = sBlo[cn * APAD + ck];
                uint32_t bl1 = sBlo[cn * APAD + ck + 4];
#pragma unroll
                for (int i = 0; i < 4; i++) {
                    mma_tf32(acc[i][j], ah[i], bh0, bh1);
                    mma_tf32(acc[i][j], ah[i], bl0, bl1);
                    mma_tf32(acc[i][j], al[i], bh0, bh1);
                }
            }
        }
    }

#pragma unroll
    for (int i = 0; i < 4; i++) {
#pragma unroll
        for (int j = 0; j < 8; j++) {
            int row = m0 + wm + i * 16 + lr;
            int cn = n0 + wn + j * 8 + lc * 2;
            *(float2*)&g_gxw[(size_t)row * G3 + cn] =
                make_float2(acc[i][j][0], acc[i][j][1]);
            *(float2*)&g_gxw[(size_t)(row + 8) * G3 + cn] =
                make_float2(acc[i][j][2], acc[i][j][3]);
        }
    }
}

// ---------------- K3: persistent recurrent (f32x2 packed cols) ----------------
// 128 CTAs x 256 threads. CTA c owns h-cols [8c, 8c+8) as 4 col-pairs.
// Warp w: col-pair cp = w>>1, batch-half = (w&1)*64. Lane mi: batches
// {half+mi, half+mi+32} x cols {base+2cp, base+2cp+1} x 3 gates = 6 f32x2
// chains. Each 32-bit lane is an independent fp32 chain with R9's exact
// per-kk association: t = h0*w0; t=fma(h1,w1,t); t=fma(h2,w2,t);
// t=fma(h3,w3,t); acc += t.
__global__ __launch_bounds__(256) void recurrent(const float* __restrict__ Whh,
                                                 const float* __restrict__ bhh,
                                                 const float* __restrict__ Wout,
                                                 const float* __restrict__ bout,
                                                 float* __restrict__ out) {
    extern __shared__ float smem[];
    float2* wpair = (float2*)smem;          // [12][1024] col-paired W
    float*  shh   = smem + 12 * 1024 * 2;   // [2][128][SHP]
    float*  sgx   = shh + 2 * BB * SHP;     // [24][GXP]
    float*  srow  = sgx + 24 * GXP;         // [1024]
    __shared__ float slog[NL];

    const int tid = threadIdx.x;
    const int cta = blockIdx.x;
    const int w   = tid >> 5;
    const int mi  = tid & 31;
    const int cp   = w >> 1;                // col-pair 0..3
    const int half = (w & 1) * 64;          // batch half
    const int base = cta * 8;
    const int col0 = base + 2 * cp, col1 = col0 + 1;
    const int bA = half + mi, bB = bA + 32;
    const int hold_kb = base & ~(KC - 1);
    const int hold_off = (base - hold_kb) + 2 * cp;

    // one-time: col-paired resident W. row p = cp*3 + gate.
    for (int idx = tid; idx < 12 * 1024; idx += 256) {
        int p = idx >> 10, k = idx & 1023;
        int pc = p / 3, gate = p - pc * 3;
        int wr0 = gate * HH + base + 2 * pc;
        wpair[p * 1024 + k] = make_float2(Whh[(size_t)wr0 * HH + k],
                                          Whh[(size_t)(wr0 + 1) * HH + k]);
    }
    const float bhr0 = bhh[col0],          bhr1 = bhh[col1];
    const float bhz0 = bhh[HH + col0],     bhz1 = bhh[HH + col1];
    const float bhn0 = bhh[2 * HH + col0], bhn1 = bhh[2 * HH + col1];
    __syncthreads();

    const float2* wpR = wpair + (cp * 3 + 0) * 1024;
    const float2* wpZ = wpair + (cp * 3 + 1) * 1024;
    const float2* wpN = wpair + (cp * 3 + 2) * 1024;

    int cur = 0;
    for (int t = 0; t < TT; t++) {
        const float* __restrict__ hin = g_hbuf[cur];
        float* __restrict__ hout = g_hbuf[cur ^ 1];

        // ---- coalesced gx staging (R9 verbatim) ----
#pragma unroll
        for (int j = 0; j < 12; j++) {
            int f = tid + j * 256;
            int gate = f >> 10;
            int b = (f >> 3) & 127;
            int c = f & 7;
            sgx[(gate * 8 + c) * GXP + b] =
                g_gxw[((size_t)b * TT + t) * G3 + gate * HH + base + c];
        }

        // ---- prefetch + store h block 0 ----
        float4 pf[8];
#pragma unroll
        for (int j = 0; j < 8; j++) {
            int f = tid + j * 256;
            int r = f >> 4, kq = f & 15;
            pf[j] = *(const float4*)&hin[r * HH + kq * 4];
        }
#pragma unroll
        for (int j = 0; j < 8; j++) {
            int f = tid + j * 256;
            int r = f >> 4, kq = f & 15;
            *(float4*)&shh[r * SHP + kq * 4] = pf[j];
        }
        __syncthreads();

        u64 arA = 0ull, azA = 0ull, anA = 0ull;
        u64 arB = 0ull, azB = 0ull, anB = 0ull;
        float2 holdA, holdB;

        for (int kb = 0; kb < HH; kb += KC) {
            const int buf = (kb >> 6) & 1;
            const float* hb = shh + buf * BB * SHP;

            // gmem prefetch of next slab (overlaps compute)
            if (kb + KC < HH) {
#pragma unroll
                for (int j = 0; j < 8; j++) {
                    int f = tid + j * 256;
                    int r = f >> 4, kq = f & 15;
                    pf[j] = *(const float4*)&hin[r * HH + kb + KC + kq * 4];
                }
            }

            if (kb == hold_kb) {
                holdA = *(const float2*)&hb[bA * SHP + hold_off];
                holdB = *(const float2*)&hb[bB * SHP + hold_off];
            }

#pragma unroll 4
            for (int kk = 0; kk < KC; kk += 4) {
                // col-paired W: {w[col0][k], w[col1][k]} per 8 bytes
                ulonglong2 wr01 = *(const ulonglong2*)&wpR[kb + kk];
                ulonglong2 wr23 = *(const ulonglong2*)&wpR[kb + kk + 2];
                ulonglong2 wz01 = *(const ulonglong2*)&wpZ[kb + kk];
                ulonglong2 wz23 = *(const ulonglong2*)&wpZ[kb + kk + 2];
                ulonglong2 wn01 = *(const ulonglong2*)&wpN[kb + kk];
                ulonglong2 wn23 = *(const ulonglong2*)&wpN[kb + kk + 2];
                float4 hA = *(const float4*)&hb[bA * SHP + kk];
                float4 hB = *(const float4*)&hb[bB * SHP + kk];
                u64 a0 = dup2(hA.x), a1 = dup2(hA.y), a2 = dup2(hA.z), a3 = dup2(hA.w);
                u64 b0 = dup2(hB.x), b1 = dup2(hB.y), b2 = dup2(hB.z), b3 = dup2(hB.w);
                u64 tacc;
                tacc = mul2(a0, wr01.x); tacc = fma2(a1, wr01.y, tacc);
                tacc = fma2(a2, wr23.x, tacc); tacc = fma2(a3, wr23.y, tacc);
                arA = add2(arA, tacc);
                tacc = mul2(a0, wz01.x); tacc = fma2(a1, wz01.y, tacc);
                tacc = fma2(a2, wz23.x, tacc); tacc = fma2(a3, wz23.y, tacc);
                azA = add2(azA, tacc);
                tacc = mul2(a0, wn01.x); tacc = fma2(a1, wn01.y, tacc);
                tacc = fma2(a2, wn23.x, tacc); tacc = fma2(a3, wn23.y, tacc);
                anA = add2(anA, tacc);
                tacc = mul2(b0, wr01.x); tacc = fma2(b1, wr01.y, tacc);
                tacc = fma2(b2, wr23.x, tacc); tacc = fma2(b3, wr23.y, tacc);
                arB = add2(arB, tacc);
                tacc = mul2(b0, wz01.x); tacc = fma2(b1, wz01.y, tacc);
                tacc = fma2(b2, wz23.x, tacc); tacc = fma2(b3, wz23.y, tacc);
                azB = add2(azB, tacc);
                tacc = mul2(b0, wn01.x); tacc = fma2(b1, wn01.y, tacc);
                tacc = fma2(b2, wn23.x, tacc); tacc = fma2(b3, wn23.y, tacc);
                anB = add2(anB, tacc);
            }

            // store prefetched next slab
            if (kb + KC < HH) {
                float* nb = shh + (buf ^ 1) * BB * SHP;
#pragma unroll
                for (int j = 0; j < 8; j++) {
                    int f = tid + j * 256;
                    int r = f >> 4, kq = f & 15;
                    *(float4*)&nb[r * SHP + kq * 4] = pf[j];
                }
            }
            __syncthreads();
        }

        // ---- epilogue: spin for prev labels, GRU update (R9 expressions) ----
        {
            float2 ar_ = upk2(arA), az_ = upk2(azA), an_ = upk2(anA);
            unsigned v = g_pt[bA];
            while ((v >> 5) < (unsigned)t) v = g_pt[bA];
            const float* tb = g_tbl + (v & 31u) * G3;
            float xr0 = sgx[(2 * cp) * GXP + bA]      + tb[col0];
            float xz0 = sgx[(8 + 2 * cp) * GXP + bA]  + tb[HH + col0];
            float xn0 = sgx[(16 + 2 * cp) * GXP + bA] + tb[2 * HH + col0];
            float r0 = sigmoidf_(xr0 + ar_.x + bhr0);
            float z0 = sigmoidf_(xz0 + az_.x + bhz0);
            float n0 = tanhf(xn0 + r0 * (an_.x + bhn0));
            float xr1 = sgx[(2 * cp + 1) * GXP + bA]      + tb[col1];
            float xz1 = sgx[(8 + 2 * cp + 1) * GXP + bA]  + tb[HH + col1];
            float xn1 = sgx[(16 + 2 * cp + 1) * GXP + bA] + tb[2 * HH + col1];
            float r1 = sigmoidf_(xr1 + ar_.y + bhr1);
            float z1 = sigmoidf_(xz1 + az_.y + bhz1);
            float n1 = tanhf(xn1 + r1 * (an_.y + bhn1));
            *(float2*)&hout[bA * HH + col0] =
                make_float2((1.0f - z0) * n0 + z0 * holdA.x,
                            (1.0f - z1) * n1 + z1 * holdA.y);
        }
        {
            float2 ar_ = upk2(arB), az_ = upk2(azB), an_ = upk2(anB);
            unsigned v = g_pt[bB];
            while ((v >> 5) < (unsigned)t) v = g_pt[bB];
            const float* tb = g_tbl + (v & 31u) * G3;
            float xr0 = sgx[(2 * cp) * GXP + bB]      + tb[col0];
            float xz0 = sgx[(8 + 2 * cp) * GXP + bB]  + tb[HH + col0];
            float xn0 = sgx[(16 + 2 * cp) * GXP + bB] + tb[2 * HH + col0];
            float r0 = sigmoidf_(xr0 + ar_.x + bhr0);
            float z0 = sigmoidf_(xz0 + az_.x + bhz0);
            float n0 = tanhf(xn0 + r0 * (an_.x + bhn0));
            float xr1 = sgx[(2 * cp + 1) * GXP + bB]      + tb[col1];
            float xz1 = sgx[(8 + 2 * cp + 1) * GXP + bB]  + tb[HH + col1];
            float xn1 = sgx[(16 + 2 * cp + 1) * GXP + bB] + tb[2 * HH + col1];
            float r1 = sigmoidf_(xr1 + ar_.y + bhr1);
            float z1 = sigmoidf_(xz1 + az_.y + bhz1);
            float n1 = tanhf(xn1 + r1 * (an_.y + bhn1));
            *(float2*)&hout[bB * HH + col0] =
                make_float2((1.0f - z0) * n0 + z0 * holdB.x,
                            (1.0f - z1) * n1 + z1 * holdB.y);
        }
        arA = azA = anA = arB = azB = anB = 0ull;

        flatbar(cta, tid, (unsigned)(t + 1));

        // ---- phase 2 (R9 verbatim): logits + masked argmax ----
        {
            const int b = cta;
            ((float4*)srow)[tid] = ((const float4*)&hout[b * HH])[tid];
            __syncthreads();
            for (int l = w; l < NL; l += 8) {
                float s = 0.0f;
                const float* wo = Wout + (size_t)l * HH;
#pragma unroll 8
                for (int k = mi; k < HH; k += 32) s += srow[k] * __ldg(&wo[k]);
#pragma unroll
                for (int off = 16; off > 0; off >>= 1)
                    s += __shfl_down_sync(0xffffffffu, s, off);
                if (mi == 0) slog[l] = s;
            }
            __syncthreads();
            if (tid == 0) {
                int pv = (int)(g_pt[b] & 31u);
                float best = -INFINITY;
                int bi = 0;
                float* orow = out + ((size_t)b * TT + t) * NL;
#pragma unroll
                for (int l = 0; l < NL; l++) {
                    float v = slog[l] + bout[l] + maskval(pv, l);
                    orow[l] = v;
                    if (v > best) { best = v; bi = l; }
                }
                g_pt[b] = ((unsigned)(t + 1) << 5) | (unsigned)bi;
            }
            __syncthreads();
        }
        cur ^= 1;
    }
}

// ---------------- launch ----------------
extern "C" void kernel_launch(void* const* d_in, const int* in_sizes, int n_in,
                              void* d_out, int out_size) {
    const float* we   = (const float*)d_in[0];
    const float* lemb = (const float*)d_in[1];
    const float* wih  = (const float*)d_in[2];
    const float* whh  = (const float*)d_in[3];
    const float* bih  = (const float*)d_in[4];
    const float* bhh  = (const float*)d_in[5];
    const float* wout = (const float*)d_in[6];
    const float* bout = (const float*)d_in[7];
    float* out = (float*)d_out;

    const int sh_gemm = (2 * 128 * APAD + 2 * 256 * APAD) * 4;              // 110,592 B
    const int sh_rec  = (12 * 1024 * 2 + 2 * BB * SHP + 24 * GXP + 1024) * 4; // 184,704 B
    cudaFuncSetAttribute(gxw_gemm_tc, cudaFuncAttributeMaxDynamicSharedMemorySize,
                         sh_gemm);
    cudaFuncSetAttribute(recurrent, cudaFuncAttributeMaxDynamicSharedMemorySize,
                         sh_rec);

    reset_state<<<512, 256>>>();
    build_table<<<dim3(G3 / 256, NL), 256>>>(lemb, wih, bih);
    presplit_A<<<4096, 256>>>(we);
    presplit_B<<<768, 256>>>(wih);
    gxw_gemm_tc<<<dim3(G3 / 256, (BB * TT) / 128), 256, sh_gemm>>>();
    recurrent<<<NCTA, 256, sh_rec>>>(whh, bhh, wout, bout, out);
}